// round 14
// baseline (speedup 1.0000x reference)
#include <cuda_runtime.h>
#include <cstdint>
#include <cstddef>

// ---------------- problem dims ----------------
#define kB   8
#define kSP  1024
#define kSF  1024
#define kS   2048
#define kXD  6
#define kD   512
#define kL   4
#define kH   8
#define kW   128
#define kDH  64
#define kC   16
#define kFF  2048
#define kM   (kB * kS)          // 16384 rows
#define kNBHC (kB * kH * kC)    // 1024

typedef unsigned long long u64;

// ---------------- scratch (__device__ globals; no runtime alloc) ----------------
__device__ float g_h   [(size_t)kB * kS * kD];
__device__ float g_ln  [(size_t)kB * kS * kD];
__device__ float g_q   [(size_t)kB * kS * kD];
__device__ float g_k   [(size_t)kB * kS * kD];
__device__ float g_v   [(size_t)kB * kS * kD];
__device__ float g_attncnt[(size_t)kB * kS * kD + (size_t)kB * kH * kS];
__device__ float g_ffn [(size_t)kB * kS * kFF];
__device__ float g_scores[(size_t)2 * kNBHC * kS];
__device__ int   g_idx [(size_t)2 * kNBHC * kW];
__device__ float g_stats[(size_t)2 * kM];            // per-row (mean, rstd)

// ---------------- helpers ----------------
__device__ __forceinline__ float gelu_tanh(float x) {
    float x3 = x * x * x;
    return 0.5f * x * (1.0f + tanhf(0.7978845608028654f * (x + 0.044715f * x3)));
}

__device__ __forceinline__ uint32_t smem_u32(const void* p) {
    uint32_t a;
    asm("{ .reg .u64 t; cvta.to.shared.u64 t, %1; cvt.u32.u64 %0, t; }" : "=r"(a) : "l"(p));
    return a;
}

__device__ __forceinline__ void cp_async16(uint32_t dst, const void* src) {
    asm volatile("cp.async.cg.shared.global [%0], [%1], 16;" :: "r"(dst), "l"(src) : "memory");
}
__device__ __forceinline__ void cp_commit() { asm volatile("cp.async.commit_group;" ::: "memory"); }
__device__ __forceinline__ void cp_wait0()  { asm volatile("cp.async.wait_group 0;" ::: "memory"); }

__device__ __forceinline__ u64 splat2(float x) {
    u64 r; asm("mov.b64 %0, {%1, %1};" : "=l"(r) : "f"(x)); return r;
}
__device__ __forceinline__ void ffma2(u64& c, u64 a, u64 b) {
    asm("fma.rn.f32x2 %0, %1, %2, %0;" : "+l"(c) : "l"(a), "l"(b));
}
__device__ __forceinline__ void unpack2(u64 v, float& lo, float& hi) {
    asm("mov.b64 {%0, %1}, %2;" : "=f"(lo), "=f"(hi) : "l"(v));
}

// ---------------- fp32 GEMM tile body (TBK=16, cp.async double-buffered) ----------------
// Per-output FMA order identical to R1 (serial k ascending).
// Optional acnt: divide A by fmax(cnt,1) at load (Wo path).
// Optional lnstats/lng/lnb: apply LN at A load, same expression as ln_kernel.
#define TBM 128
#define TBN 128
#define TBK 16
__device__ __forceinline__ void gemm_body(
    const float* __restrict__ A, const float* __restrict__ Bm,
    const float* __restrict__ bias, const float* __restrict__ res,
    const float* __restrict__ acnt,
    const float* __restrict__ lnstats, const float* __restrict__ lng,
    const float* __restrict__ lnb,
    float* __restrict__ Cm, int M, int N, int K, int act, int bx, int by) {
    __shared__ float As[2][TBK][TBM];
    __shared__ float Bs[2][TBK][TBN];
    int tid = threadIdx.x;
    int tx = tid % 16, ty = tid / 16;
    const float* Ab = A + (size_t)by * TBM * K;
    const float* Bb = Bm + (size_t)bx * TBN;

    u64 accp[4][8];
#pragma unroll
    for (int ip = 0; ip < 4; ip++)
#pragma unroll
        for (int j = 0; j < 8; j++) accp[ip][j] = 0ull;

    int aRow = tid >> 1, aCol = (tid & 1) * 8;
    int bRow = tid >> 5, bCol = (tid & 31) * 4;

    uint32_t bs_base = smem_u32(&Bs[0][0][0]);
    const float* Aptr = Ab + (size_t)aRow * K + aCol;

    int grow = by * TBM + aRow;
    int cb = grow / kS, cs = grow % kS;
    const float* cnt_row = acnt ? acnt + ((size_t)cb * kH) * kS + cs : nullptr;
    float mean = 0.f, rstd = 0.f;
    if (lnstats) { mean = lnstats[2 * grow]; rstd = lnstats[2 * grow + 1]; }

    {
        cp_async16(bs_base + ((size_t)(0 * TBK + bRow) * TBN + bCol) * 4,
                   Bb + (size_t)bRow * N + bCol);
        cp_async16(bs_base + ((size_t)(0 * TBK + bRow + 8) * TBN + bCol) * 4,
                   Bb + (size_t)(bRow + 8) * N + bCol);
        cp_commit();
        float4 a0 = *(const float4*)(Aptr);
        float4 a1 = *(const float4*)(Aptr + 4);
        if (cnt_row) {
            int hh = aCol >> 6;
            float c = fmaxf(cnt_row[(size_t)hh * kS], 1.0f);
            a0.x /= c; a0.y /= c; a0.z /= c; a0.w /= c;
            a1.x /= c; a1.y /= c; a1.z /= c; a1.w /= c;
        }
        if (lnstats) {
            float4 g0 = *(const float4*)(lng + aCol);
            float4 g1 = *(const float4*)(lng + aCol + 4);
            float4 b0 = *(const float4*)(lnb + aCol);
            float4 b1 = *(const float4*)(lnb + aCol + 4);
            a0.x = (a0.x - mean) * rstd * g0.x + b0.x;
            a0.y = (a0.y - mean) * rstd * g0.y + b0.y;
            a0.z = (a0.z - mean) * rstd * g0.z + b0.z;
            a0.w = (a0.w - mean) * rstd * g0.w + b0.w;
            a1.x = (a1.x - mean) * rstd * g1.x + b1.x;
            a1.y = (a1.y - mean) * rstd * g1.y + b1.y;
            a1.z = (a1.z - mean) * rstd * g1.z + b1.z;
            a1.w = (a1.w - mean) * rstd * g1.w + b1.w;
        }
        As[0][aCol + 0][aRow] = a0.x; As[0][aCol + 1][aRow] = a0.y;
        As[0][aCol + 2][aRow] = a0.z; As[0][aCol + 3][aRow] = a0.w;
        As[0][aCol + 4][aRow] = a1.x; As[0][aCol + 5][aRow] = a1.y;
        As[0][aCol + 6][aRow] = a1.z; As[0][aCol + 7][aRow] = a1.w;
        cp_wait0();
    }
    __syncthreads();

    int nk = K / TBK;
    for (int kb = 0; kb < nk; kb++) {
        int cur = kb & 1, nxt = cur ^ 1;
        float4 a0, a1;
        bool pf = (kb + 1 < nk);
        if (pf) {
            int k0 = (kb + 1) * TBK;
            cp_async16(bs_base + ((size_t)(nxt * TBK + bRow) * TBN + bCol) * 4,
                       Bb + (size_t)(k0 + bRow) * N + bCol);
            cp_async16(bs_base + ((size_t)(nxt * TBK + bRow + 8) * TBN + bCol) * 4,
                       Bb + (size_t)(k0 + bRow + 8) * N + bCol);
            cp_commit();
            a0 = *(const float4*)(Aptr + k0);
            a1 = *(const float4*)(Aptr + k0 + 4);
            if (cnt_row) {
                int hh = (k0 + aCol) >> 6;
                float c = fmaxf(cnt_row[(size_t)hh * kS], 1.0f);
                a0.x /= c; a0.y /= c; a0.z /= c; a0.w /= c;
                a1.x /= c; a1.y /= c; a1.z /= c; a1.w /= c;
            }
            if (lnstats) {
                float4 g0 = *(const float4*)(lng + k0 + aCol);
                float4 g1 = *(const float4*)(lng + k0 + aCol + 4);
                float4 b0 = *(const float4*)(lnb + k0 + aCol);
                float4 b1 = *(const float4*)(lnb + k0 + aCol + 4);
                a0.x = (a0.x - mean) * rstd * g0.x + b0.x;
                a0.y = (a0.y - mean) * rstd * g0.y + b0.y;
                a0.z = (a0.z - mean) * rstd * g0.z + b0.z;
                a0.w = (a0.w - mean) * rstd * g0.w + b0.w;
                a1.x = (a1.x - mean) * rstd * g1.x + b1.x;
                a1.y = (a1.y - mean) * rstd * g1.y + b1.y;
                a1.z = (a1.z - mean) * rstd * g1.z + b1.z;
                a1.w = (a1.w - mean) * rstd * g1.w + b1.w;
            }
        }
#pragma unroll
        for (int k = 0; k < TBK; k++) {
            u64 ap[4];
            *(float4*)(&ap[0]) = *(const float4*)(&As[cur][k][ty * 8 + 0]);
            *(float4*)(&ap[2]) = *(const float4*)(&As[cur][k][ty * 8 + 4]);
            float br[8];
            *(float4*)(br + 0) = *(const float4*)(&Bs[cur][k][tx * 8 + 0]);
            *(float4*)(br + 4) = *(const float4*)(&Bs[cur][k][tx * 8 + 4]);
            u64 bd[8];
#pragma unroll
            for (int j = 0; j < 8; j++) bd[j] = splat2(br[j]);
#pragma unroll
            for (int ip = 0; ip < 4; ip++)
#pragma unroll
                for (int j = 0; j < 8; j++) ffma2(accp[ip][j], ap[ip], bd[j]);
        }
        if (pf) {
            As[nxt][aCol + 0][aRow] = a0.x; As[nxt][aCol + 1][aRow] = a0.y;
            As[nxt][aCol + 2][aRow] = a0.z; As[nxt][aCol + 3][aRow] = a0.w;
            As[nxt][aCol + 4][aRow] = a1.x; As[nxt][aCol + 5][aRow] = a1.y;
            As[nxt][aCol + 6][aRow] = a1.z; As[nxt][aCol + 7][aRow] = a1.w;
            cp_wait0();
        }
        __syncthreads();
    }

#pragma unroll
    for (int ip = 0; ip < 4; ip++) {
#pragma unroll
        for (int half = 0; half < 2; half++) {
            int i = ip * 2 + half;
            int row = by * TBM + ty * 8 + i;
            int col0 = bx * TBN + tx * 8;
            float* crow = Cm + (size_t)row * N + col0;
            const float* rrow = res ? res + (size_t)row * N + col0 : nullptr;
#pragma unroll
            for (int j = 0; j < 8; j++) {
                float lo, hi;
                unpack2(accp[ip][j], lo, hi);
                float v = half ? hi : lo;
                if (bias) v += bias[col0 + j];
                if (rrow) v += rrow[j];
                if (act) v = gelu_tanh(v);
                crow[j] = v;
            }
        }
    }
}

__global__ __launch_bounds__(256, 2) void sgemm_kernel(
    const float* __restrict__ A, const float* __restrict__ Bm,
    const float* __restrict__ bias, const float* __restrict__ res,
    const float* __restrict__ acnt,
    const float* __restrict__ lnstats, const float* __restrict__ lng,
    const float* __restrict__ lnb,
    float* __restrict__ Cm, int M, int N, int K, int act) {
    gemm_body(A, Bm, bias, res, acnt, lnstats, lng, lnb, Cm, M, N, K, act,
              blockIdx.x, blockIdx.y);
}

__global__ __launch_bounds__(256, 2) void qkv_gemm_kernel(
    const float* __restrict__ A,
    const float* __restrict__ Bq, const float* __restrict__ Bk, const float* __restrict__ Bv,
    const float* __restrict__ lnstats, const float* __restrict__ lng,
    const float* __restrict__ lnb,
    float* __restrict__ Cq, float* __restrict__ Ck, float* __restrict__ Cv,
    int M, int N, int K) {
    const float* Bm = (blockIdx.z == 0) ? Bq : (blockIdx.z == 1) ? Bk : Bv;
    float* Cm = (blockIdx.z == 0) ? Cq : (blockIdx.z == 1) ? Ck : Cv;
    gemm_body(A, Bm, nullptr, nullptr, nullptr, lnstats, lng, lnb, Cm, M, N, K, 0,
              blockIdx.x, blockIdx.y);
}

// ---------------- embedding ----------------
__global__ void embed_kernel(const float* __restrict__ past_x,
                             const float* __restrict__ past_y,
                             const float* __restrict__ future_x,
                             const float* __restrict__ W_emb,
                             const float* __restrict__ b_emb,
                             float* __restrict__ h) {
    int idx = blockIdx.x * blockDim.x + threadIdx.x;
    if (idx >= kB * kS * kD) return;
    int d = idx % kD;
    int s = (idx / kD) % kS;
    int b = idx / (kD * kS);
    float feat[kXD + 1];
    if (s < kSP) {
#pragma unroll
        for (int j = 0; j < kXD; j++) feat[j] = past_x[((size_t)b * kSP + s) * kXD + j];
        feat[kXD] = past_y[(size_t)b * kSP + s];
    } else {
        int sf = s - kSP;
#pragma unroll
        for (int j = 0; j < kXD; j++) feat[j] = future_x[((size_t)b * kSF + sf) * kXD + j];
        feat[kXD] = past_y[(size_t)b * kSP + (kSP - 1)];
    }
    float acc = b_emb[d];
#pragma unroll
    for (int j = 0; j < kXD + 1; j++) acc += feat[j] * W_emb[(size_t)j * kD + d];
    h[idx] = acc;
}

// ---------------- LN stats (same reduction tree as ln_kernel) ----------------
__global__ void ln_stats_kernel(const float* __restrict__ x, float* __restrict__ stats) {
    __shared__ float red[8];
    int row = blockIdx.x;
    int t = threadIdx.x;
    const float4 xv = ((const float4*)(x + (size_t)row * kD))[t];
    float s = xv.x + xv.y + xv.z + xv.w;
#pragma unroll
    for (int o = 16; o; o >>= 1) s += __shfl_xor_sync(0xffffffffu, s, o);
    if ((t & 31) == 0) red[t >> 5] = s;
    __syncthreads();
    float mean = (red[0] + red[1] + red[2] + red[3]) * (1.0f / kD);
    float dx = xv.x - mean, dy = xv.y - mean, dz = xv.z - mean, dw = xv.w - mean;
    float s2 = dx * dx + dy * dy + dz * dz + dw * dw;
#pragma unroll
    for (int o = 16; o; o >>= 1) s2 += __shfl_xor_sync(0xffffffffu, s2, o);
    if ((t & 31) == 0) red[4 + (t >> 5)] = s2;
    __syncthreads();
    if (t == 0) {
        float var = (red[4] + red[5] + red[6] + red[7]) * (1.0f / kD);
        stats[2 * row] = mean;
        stats[2 * row + 1] = rsqrtf(var + 1e-5f);
    }
}

// ---------------- full layernorm (final LN only; future rows) ----------------
__global__ void ln_kernel(const float* __restrict__ x, float* __restrict__ y,
                          const float* __restrict__ g, const float* __restrict__ bb,
                          int futureOnly) {
    __shared__ float red[8];
    int blk = blockIdx.x;
    int row = futureOnly ? (blk / kSF) * kS + kSP + (blk % kSF) : blk;
    int t = threadIdx.x;
    const float4 xv = ((const float4*)(x + (size_t)row * kD))[t];
    float s = xv.x + xv.y + xv.z + xv.w;
#pragma unroll
    for (int o = 16; o; o >>= 1) s += __shfl_xor_sync(0xffffffffu, s, o);
    if ((t & 31) == 0) red[t >> 5] = s;
    __syncthreads();
    float mean = (red[0] + red[1] + red[2] + red[3]) * (1.0f / kD);
    float dx = xv.x - mean, dy = xv.y - mean, dz = xv.z - mean, dw = xv.w - mean;
    float s2 = dx * dx + dy * dy + dz * dz + dw * dw;
#pragma unroll
    for (int o = 16; o; o >>= 1) s2 += __shfl_xor_sync(0xffffffffu, s2, o);
    if ((t & 31) == 0) red[4 + (t >> 5)] = s2;
    __syncthreads();
    float var = (red[4] + red[5] + red[6] + red[7]) * (1.0f / kD);
    float rstd = rsqrtf(var + 1e-5f);
    const float4 gg = ((const float4*)g)[t];
    const float4 bv = ((const float4*)bb)[t];
    float4 o4;
    o4.x = dx * rstd * gg.x + bv.x;
    o4.y = dy * rstd * gg.y + bv.y;
    o4.z = dz * rstd * gg.z + bv.z;
    o4.w = dw * rstd * gg.w + bv.w;
    ((float4*)(y + (size_t)row * kD))[t] = o4;
}

// ---------------- routing scores: shuffle-free, bit-identical reduction tree ----------------
__global__ __launch_bounds__(128) void score2_kernel(
    const float* __restrict__ q, const float* __restrict__ k,
    const float* __restrict__ means, float* __restrict__ scores) {
    int blk = blockIdx.x;
    int inst = blk >> 10;
    int rem = blk & 1023;
    int b = rem >> 7;
    int h = (rem >> 4) & 7;
    int st = rem & 15;
    const float* src = inst ? k : q;
    float* dst = scores + (size_t)inst * kNBHC * kS;
    int t = threadIdx.x;
    int s = st * 128 + t;

    __shared__ float ms[kC * kDH];
    for (int i = t; i < kC * kDH; i += 128)
        ms[i] = means[(size_t)h * kC * kDH + i];
    __syncthreads();

    float qv[kDH];
    const float4* qrow = (const float4*)(src + ((size_t)b * kS + s) * kD + h * kDH);
#pragma unroll
    for (int i = 0; i < kDH / 4; i++) ((float4*)qv)[i] = qrow[i];

    float p[32];
#pragma unroll
    for (int l = 0; l < 32; l++) p[l] = qv[l] * qv[l] + qv[l + 32] * qv[l + 32];
#pragma unroll
    for (int o = 16; o; o >>= 1)
#pragma unroll
        for (int l = 0; l < o; l++) p[l] += p[l + o];
    float rn = rsqrtf(p[0] + 1e-8f);

    float* out = dst + (((size_t)b * kH + h) * kC) * kS + s;
#pragma unroll
    for (int c = 0; c < kC; c++) {
        const float* mrow = ms + c * kDH;
        float pp[32];
#pragma unroll
        for (int l = 0; l < 32; l++) pp[l] = qv[l] * mrow[l] + qv[l + 32] * mrow[l + 32];
#pragma unroll
        for (int o = 16; o; o >>= 1)
#pragma unroll
            for (int l = 0; l < o; l++) pp[l] += pp[l + o];
        out[(size_t)c * kS] = pp[0] * rn;
    }
}

// ---------------- top-W: bitonic sort stages + prefix bitonic-splits ----------------
__global__ __launch_bounds__(512) void topk_kernel(const float* __restrict__ scores,
                                                   int* __restrict__ idxout) {
    __shared__ unsigned long long keys[kS];
    int blk = blockIdx.x;
    const float* sp = scores + (size_t)blk * kS;
    for (int i = threadIdx.x; i < kS; i += 512) {
        unsigned u = __float_as_uint(sp[i]);
        u = (u & 0x80000000u) ? ~u : (u | 0x80000000u);
        keys[i] = ((unsigned long long)u << 32) | (unsigned)i;
    }
    __syncthreads();
    for (int k = 2; k <= 1024; k <<= 1) {
        for (int j = k >> 1; j > 0; j >>= 1) {
            for (int i = threadIdx.x; i < kS; i += 512) {
                int ixj = i ^ j;
                if (ixj > i) {
                    unsigned long long a = keys[i], b = keys[ixj];
                    bool up = ((i & k) == 0);
                    bool sw = up ? (a < b) : (a > b);
                    if (sw) { keys[i] = b; keys[ixj] = a; }
                }
            }
            __syncthreads();
        }
    }
#pragma unroll
    for (int half = 1024; half >= 128; half >>= 1) {
        for (int i = threadIdx.x; i < half; i += 512) {
            unsigned long long a = keys[i], b = keys[i + half];
            if (a < b) { keys[i] = b; keys[i + half] = a; }
        }
        __syncthreads();
    }
    if (threadIdx.x < kW)
        idxout[(size_t)blk * kW + threadIdx.x] = (int)(keys[threadIdx.x] & 0xffffffffu);
}

// ---------------- within-cluster attention + scatter-add ----------------
__global__ __launch_bounds__(128) void attn_kernel(
    const float* __restrict__ q, const float* __restrict__ k, const float* __restrict__ v,
    const int* __restrict__ iq, const int* __restrict__ ik,
    float* __restrict__ attnout, float* __restrict__ cnt) {
    int blk = blockIdx.x;
    int h = (blk / kC) % kH;
    int b = blk / (kC * kH);
    extern __shared__ float smem[];
    float* ks = smem;
    float* vs = smem + kW * kDH;
    int t = threadIdx.x;
    const int* ikp = ik + (size_t)blk * kW;
    const int* iqp = iq + (size_t)blk * kW;
    {
        int sk = ikp[t];
        const float4* krow = (const float4*)(k + ((size_t)b * kS + sk) * kD + h * kDH);
        const float4* vrow = (const float4*)(v + ((size_t)b * kS + sk) * kD + h * kDH);
        float4* ksr = (float4*)(ks + (size_t)t * kDH);
        float4* vsr = (float4*)(vs + (size_t)t * kDH);
#pragma unroll
        for (int i = 0; i < kDH / 4; i++) { ksr[i] = krow[i]; vsr[i] = vrow[i]; }
    }
    __syncthreads();
    int sq = iqp[t];
    float qreg[kDH];
    {
        const float4* qrow = (const float4*)(q + ((size_t)b * kS + sq) * kD + h * kDH);
#pragma unroll
        for (int i = 0; i < kDH / 4; i++) ((float4*)qreg)[i] = qrow[i];
    }
    float m = -1e30f, l = 0.f;
    float accv[kDH];
#pragma unroll
    for (int d = 0; d < kDH; d++) accv[d] = 0.f;
    const float scale = 0.125f;

    for (int j = 0; j < kW; j++) {
        const float* kj = ks + (size_t)j * kDH;
        float s0 = 0, s1 = 0, s2 = 0, s3 = 0;
#pragma unroll
        for (int d = 0; d < kDH; d += 4) {
            s0 += qreg[d + 0] * kj[d + 0];
            s1 += qreg[d + 1] * kj[d + 1];
            s2 += qreg[d + 2] * kj[d + 2];
            s3 += qreg[d + 3] * kj[d + 3];
        }
        float s = (s0 + s1 + s2 + s3) * scale;
        const float* vj = vs + (size_t)j * kDH;
        if (s > m) {
            float corr = __expf(m - s);
            l = fmaf(l, corr, 1.0f);
#pragma unroll
            for (int d = 0; d < kDH; d++) accv[d] = fmaf(accv[d], corr, vj[d]);
            m = s;
        } else {
            float p = __expf(s - m);
            l += p;
#pragma unroll
            for (int d = 0; d < kDH; d++) accv[d] = fmaf(p, vj[d], accv[d]);
        }
    }
    float inv = 1.0f / l;
    float* orow = attnout + ((size_t)b * kS + sq) * kD + h * kDH;
#pragma unroll
    for (int d = 0; d < kDH; d++) atomicAdd(orow + d, accv[d] * inv);
    atomicAdd(cnt + ((size_t)b * kH + h) * kS + sq, 1.0f);
}

// ---------------- output heads ----------------
__global__ void head_kernel(const float* __restrict__ hln,
                            const float* __restrict__ Wm, const float* __restrict__ bm,
                            const float* __restrict__ Ws, const float* __restrict__ bsd,
                            float* __restrict__ out) {
    int warp = (blockIdx.x * blockDim.x + threadIdx.x) >> 5;
    int lane = threadIdx.x & 31;
    if (warp >= kB * kSF) return;
    int b = warp / kSF, sf = warp % kSF;
    const float* row = hln + ((size_t)b * kS + kSP + sf) * kD;
    float mdot = 0.f, sdot = 0.f;
    for (int d = lane; d < kD; d += 32) {
        float x = row[d];
        mdot += x * Wm[d];
        sdot += x * Ws[d];
    }
#pragma unroll
    for (int o = 16; o; o >>= 1) {
        mdot += __shfl_xor_sync(0xffffffffu, mdot, o);
        sdot += __shfl_xor_sync(0xffffffffu, sdot, o);
    }
    if (lane == 0) {
        out[warp] = mdot + bm[0];
        float ls = sdot + bsd[0];
        float sp = fmaxf(ls, 0.f) + log1pf(__expf(-fabsf(ls)));
        out[(size_t)kB * kSF + warp] = 0.01f + 0.99f * sp;
    }
}

// ---------------- host orchestration ----------------
static void launch_gemm(const float* A, const float* Bm, const float* bias,
                        const float* res, const float* acnt,
                        const float* lnstats, const float* lng, const float* lnb,
                        float* C, int M, int N, int K, int act) {
    dim3 grid(N / TBN, M / TBM);
    sgemm_kernel<<<grid, 256>>>(A, Bm, bias, res, acnt, lnstats, lng, lnb, C, M, N, K, act);
}

extern "C" void kernel_launch(void* const* d_in, const int* in_sizes, int n_in,
                              void* d_out, int out_size) {
    const float* past_x   = (const float*)d_in[0];
    const float* past_y   = (const float*)d_in[1];
    const float* future_x = (const float*)d_in[2];
    const float* W_emb    = (const float*)d_in[3];
    const float* b_emb    = (const float*)d_in[4];
    const float* ln1_g    = (const float*)d_in[5];
    const float* ln1_b    = (const float*)d_in[6];
    const float* Wq       = (const float*)d_in[7];
    const float* Wk       = (const float*)d_in[8];
    const float* Wv       = (const float*)d_in[9];
    const float* Wo       = (const float*)d_in[10];
    const float* means    = (const float*)d_in[11];
    const float* ln2_g    = (const float*)d_in[12];
    const float* ln2_b    = (const float*)d_in[13];
    const float* W1       = (const float*)d_in[14];
    const float* b1       = (const float*)d_in[15];
    const float* W2       = (const float*)d_in[16];
    const float* b2       = (const float*)d_in[17];
    const float* lnf_g    = (const float*)d_in[18];
    const float* lnf_b    = (const float*)d_in[19];
    const float* W_mean   = (const float*)d_in[20];
    const float* b_mean   = (const float*)d_in[21];
    const float* W_std    = (const float*)d_in[22];
    const float* b_std    = (const float*)d_in[23];

    void *ph, *pln, *pq, *pk, *pv, *pac, *pffn, *pscores, *pidx, *pst;
    cudaGetSymbolAddress(&ph, g_h);
    cudaGetSymbolAddress(&pln, g_ln);
    cudaGetSymbolAddress(&pq, g_q);
    cudaGetSymbolAddress(&pk, g_k);
    cudaGetSymbolAddress(&pv, g_v);
    cudaGetSymbolAddress(&pac, g_attncnt);
    cudaGetSymbolAddress(&pffn, g_ffn);
    cudaGetSymbolAddress(&pscores, g_scores);
    cudaGetSymbolAddress(&pidx, g_idx);
    cudaGetSymbolAddress(&pst, g_stats);
    float* h    = (float*)ph;
    float* ln   = (float*)pln;
    float* q    = (float*)pq;
    float* k    = (float*)pk;
    float* v    = (float*)pv;
    float* attn = (float*)pac;
    float* cnt  = (float*)pac + (size_t)kB * kS * kD;
    float* ffn  = (float*)pffn;
    float* scr  = (float*)pscores;
    int*   iq   = (int*)pidx;
    int*   ik   = (int*)pidx + (size_t)kNBHC * kW;
    float* stats = (float*)pst;

    const int attn_smem = 2 * kW * kDH * (int)sizeof(float);  // 64 KB
    cudaFuncSetAttribute(attn_kernel, cudaFuncAttributeMaxDynamicSharedMemorySize, attn_smem);

    {
        int total = kB * kS * kD;
        embed_kernel<<<(total + 255) / 256, 256>>>(past_x, past_y, future_x, W_emb, b_emb, h);
    }

    const size_t attncnt_bytes = ((size_t)kB * kS * kD + (size_t)kB * kH * kS) * sizeof(float);

    for (int l = 0; l < kL; l++) {
        const float* mns = means + (size_t)l * kH * kC * kDH;
        // --- attention block: LN1 stats, then LN applied inside QKV A-load ---
        ln_stats_kernel<<<kM, 128>>>(h, stats);
        {
            dim3 grid(kD / TBN, kM / TBM, 3);
            qkv_gemm_kernel<<<grid, 256>>>(
                h, Wq + (size_t)l * kD * kD, Wk + (size_t)l * kD * kD, Wv + (size_t)l * kD * kD,
                stats, ln1_g + (size_t)l * kD, ln1_b + (size_t)l * kD,
                q, k, v, kM, kD, kD);
        }

        score2_kernel<<<2 * kB * kH * (kS / 128), 128>>>(q, k, mns, scr);
        topk_kernel<<<2 * kNBHC, 512>>>(scr, (int*)pidx);

        cudaMemsetAsync(attn, 0, attncnt_bytes, 0);
        attn_kernel<<<kNBHC, 128, attn_smem>>>(q, k, v, iq, ik, attn, cnt);

        // h = h + (attn/cnt) @ Wo
        launch_gemm(attn, Wo + (size_t)l * kD * kD, nullptr, h, cnt,
                    nullptr, nullptr, nullptr, h, kM, kD, kD, 0);

        // --- FFN block: LN2 stats, LN applied inside W1 A-load ---
        ln_stats_kernel<<<kM, 128>>>(h, stats);
        launch_gemm(h, W1 + (size_t)l * kD * kFF, b1 + (size_t)l * kFF, nullptr, nullptr,
                    stats, ln2_g + (size_t)l * kD, ln2_b + (size_t)l * kD,
                    ffn, kM, kFF, kD, 1);
        launch_gemm(ffn, W2 + (size_t)l * kFF * kD, b2 + (size_t)l * kD, h, nullptr,
                    nullptr, nullptr, nullptr, h, kM, kD, kFF, 0);
    }

    // final LN + heads: only the future half is consumed
    ln_kernel<<<kB * kSF, 128>>>(h, ln, lnf_g, lnf_b, 1);
    {
        int warps = kB * kSF;
        int threads = warps * 32;
        head_kernel<<<(threads + 255) / 256, 256>>>(ln, W_mean, b_mean, W_std, b_std, (float*)d_out);
    }
}

// round 16
// speedup vs baseline: 1.0531x; 1.0531x over previous
#include <cuda_runtime.h>
#include <cstdint>
#include <cstddef>

// ---------------- problem dims ----------------
#define kB   8
#define kSP  1024
#define kSF  1024
#define kS   2048
#define kXD  6
#define kD   512
#define kL   4
#define kH   8
#define kW   128
#define kDH  64
#define kC   16
#define kFF  2048
#define kM   (kB * kS)          // 16384 rows
#define kNBHC (kB * kH * kC)    // 1024

typedef unsigned long long u64;

// ---------------- scratch (__device__ globals; no runtime alloc) ----------------
__device__ float g_h   [(size_t)kB * kS * kD];
__device__ float g_ln  [(size_t)kB * kS * kD];
__device__ float g_q   [(size_t)kB * kS * kD];
__device__ float g_k   [(size_t)kB * kS * kD];
__device__ float g_v   [(size_t)kB * kS * kD];
__device__ float g_attncnt[(size_t)kB * kS * kD + (size_t)kB * kH * kS];
__device__ float g_ffn [(size_t)kB * kS * kFF];
__device__ float g_scores[(size_t)2 * kNBHC * kS];
__device__ int   g_idx [(size_t)2 * kNBHC * kW];

// ---------------- helpers ----------------
__device__ __forceinline__ float gelu_tanh(float x) {
    float x3 = x * x * x;
    return 0.5f * x * (1.0f + tanhf(0.7978845608028654f * (x + 0.044715f * x3)));
}

__device__ __forceinline__ uint32_t smem_u32(const void* p) {
    uint32_t a;
    asm("{ .reg .u64 t; cvta.to.shared.u64 t, %1; cvt.u32.u64 %0, t; }" : "=r"(a) : "l"(p));
    return a;
}

__device__ __forceinline__ void cp_async16(uint32_t dst, const void* src) {
    asm volatile("cp.async.cg.shared.global [%0], [%1], 16;" :: "r"(dst), "l"(src) : "memory");
}
__device__ __forceinline__ void cp_commit() { asm volatile("cp.async.commit_group;" ::: "memory"); }
__device__ __forceinline__ void cp_wait0()  { asm volatile("cp.async.wait_group 0;" ::: "memory"); }

__device__ __forceinline__ u64 splat2(float x) {
    u64 r; asm("mov.b64 %0, {%1, %1};" : "=l"(r) : "f"(x)); return r;
}
__device__ __forceinline__ void ffma2(u64& c, u64 a, u64 b) {
    asm("fma.rn.f32x2 %0, %1, %2, %0;" : "+l"(c) : "l"(a), "l"(b));
}
__device__ __forceinline__ void unpack2(u64 v, float& lo, float& hi) {
    asm("mov.b64 {%0, %1}, %2;" : "=f"(lo), "=f"(hi) : "l"(v));
}

// ---------------- fp32 GEMM tile body (TBK=16, cp.async double-buffered) ----------------
#define TBM 128
#define TBN 128
#define TBK 16
__device__ __forceinline__ void gemm_body(
    const float* __restrict__ A, const float* __restrict__ Bm,
    const float* __restrict__ bias, const float* __restrict__ res,
    const float* __restrict__ acnt,
    float* __restrict__ Cm, int M, int N, int K, int act, int bx, int by) {
    __shared__ float As[2][TBK][TBM];
    __shared__ float Bs[2][TBK][TBN];
    int tid = threadIdx.x;
    int tx = tid % 16, ty = tid / 16;
    const float* Ab = A + (size_t)by * TBM * K;
    const float* Bb = Bm + (size_t)bx * TBN;

    u64 accp[4][8];
#pragma unroll
    for (int ip = 0; ip < 4; ip++)
#pragma unroll
        for (int j = 0; j < 8; j++) accp[ip][j] = 0ull;

    int aRow = tid >> 1, aCol = (tid & 1) * 8;
    int bRow = tid >> 5, bCol = (tid & 31) * 4;

    uint32_t bs_base = smem_u32(&Bs[0][0][0]);
    const float* Aptr = Ab + (size_t)aRow * K + aCol;

    int grow = by * TBM + aRow;
    int cb = grow / kS, cs = grow % kS;
    const float* cnt_row = acnt ? acnt + ((size_t)cb * kH) * kS + cs : nullptr;

    {
        cp_async16(bs_base + ((size_t)(0 * TBK + bRow) * TBN + bCol) * 4,
                   Bb + (size_t)bRow * N + bCol);
        cp_async16(bs_base + ((size_t)(0 * TBK + bRow + 8) * TBN + bCol) * 4,
                   Bb + (size_t)(bRow + 8) * N + bCol);
        cp_commit();
        float4 a0 = *(const float4*)(Aptr);
        float4 a1 = *(const float4*)(Aptr + 4);
        if (cnt_row) {
            int hh = aCol >> 6;
            float c = fmaxf(cnt_row[(size_t)hh * kS], 1.0f);
            a0.x /= c; a0.y /= c; a0.z /= c; a0.w /= c;
            a1.x /= c; a1.y /= c; a1.z /= c; a1.w /= c;
        }
        As[0][aCol + 0][aRow] = a0.x; As[0][aCol + 1][aRow] = a0.y;
        As[0][aCol + 2][aRow] = a0.z; As[0][aCol + 3][aRow] = a0.w;
        As[0][aCol + 4][aRow] = a1.x; As[0][aCol + 5][aRow] = a1.y;
        As[0][aCol + 6][aRow] = a1.z; As[0][aCol + 7][aRow] = a1.w;
        cp_wait0();
    }
    __syncthreads();

    int nk = K / TBK;
    for (int kb = 0; kb < nk; kb++) {
        int cur = kb & 1, nxt = cur ^ 1;
        float4 a0, a1;
        bool pf = (kb + 1 < nk);
        if (pf) {
            int k0 = (kb + 1) * TBK;
            cp_async16(bs_base + ((size_t)(nxt * TBK + bRow) * TBN + bCol) * 4,
                       Bb + (size_t)(k0 + bRow) * N + bCol);
            cp_async16(bs_base + ((size_t)(nxt * TBK + bRow + 8) * TBN + bCol) * 4,
                       Bb + (size_t)(k0 + bRow + 8) * N + bCol);
            cp_commit();
            a0 = *(const float4*)(Aptr + k0);
            a1 = *(const float4*)(Aptr + k0 + 4);
            if (cnt_row) {
                int hh = (k0 + aCol) >> 6;
                float c = fmaxf(cnt_row[(size_t)hh * kS], 1.0f);
                a0.x /= c; a0.y /= c; a0.z /= c; a0.w /= c;
                a1.x /= c; a1.y /= c; a1.z /= c; a1.w /= c;
            }
        }
#pragma unroll
        for (int k = 0; k < TBK; k++) {
            u64 ap[4];
            *(float4*)(&ap[0]) = *(const float4*)(&As[cur][k][ty * 8 + 0]);
            *(float4*)(&ap[2]) = *(const float4*)(&As[cur][k][ty * 8 + 4]);
            float br[8];
            *(float4*)(br + 0) = *(const float4*)(&Bs[cur][k][tx * 8 + 0]);
            *(float4*)(br + 4) = *(const float4*)(&Bs[cur][k][tx * 8 + 4]);
            u64 bd[8];
#pragma unroll
            for (int j = 0; j < 8; j++) bd[j] = splat2(br[j]);
#pragma unroll
            for (int ip = 0; ip < 4; ip++)
#pragma unroll
                for (int j = 0; j < 8; j++) ffma2(accp[ip][j], ap[ip], bd[j]);
        }
        if (pf) {
            As[nxt][aCol + 0][aRow] = a0.x; As[nxt][aCol + 1][aRow] = a0.y;
            As[nxt][aCol + 2][aRow] = a0.z; As[nxt][aCol + 3][aRow] = a0.w;
            As[nxt][aCol + 4][aRow] = a1.x; As[nxt][aCol + 5][aRow] = a1.y;
            As[nxt][aCol + 6][aRow] = a1.z; As[nxt][aCol + 7][aRow] = a1.w;
            cp_wait0();
        }
        __syncthreads();
    }

#pragma unroll
    for (int ip = 0; ip < 4; ip++) {
#pragma unroll
        for (int half = 0; half < 2; half++) {
            int i = ip * 2 + half;
            int row = by * TBM + ty * 8 + i;
            int col0 = bx * TBN + tx * 8;
            float* crow = Cm + (size_t)row * N + col0;
            const float* rrow = res ? res + (size_t)row * N + col0 : nullptr;
#pragma unroll
            for (int j = 0; j < 8; j++) {
                float lo, hi;
                unpack2(accp[ip][j], lo, hi);
                float v = half ? hi : lo;
                if (bias) v += bias[col0 + j];
                if (rrow) v += rrow[j];
                if (act) v = gelu_tanh(v);
                crow[j] = v;
            }
        }
    }
}

__global__ __launch_bounds__(256, 2) void sgemm_kernel(
    const float* __restrict__ A, const float* __restrict__ Bm,
    const float* __restrict__ bias, const float* __restrict__ res,
    const float* __restrict__ acnt,
    float* __restrict__ Cm, int M, int N, int K, int act) {
    gemm_body(A, Bm, bias, res, acnt, Cm, M, N, K, act, blockIdx.x, blockIdx.y);
}

__global__ __launch_bounds__(256, 2) void qkv_gemm_kernel(
    const float* __restrict__ A,
    const float* __restrict__ Bq, const float* __restrict__ Bk, const float* __restrict__ Bv,
    float* __restrict__ Cq, float* __restrict__ Ck, float* __restrict__ Cv,
    int M, int N, int K) {
    const float* Bm = (blockIdx.z == 0) ? Bq : (blockIdx.z == 1) ? Bk : Bv;
    float* Cm = (blockIdx.z == 0) ? Cq : (blockIdx.z == 1) ? Ck : Cv;
    gemm_body(A, Bm, nullptr, nullptr, nullptr, Cm, M, N, K, 0, blockIdx.x, blockIdx.y);
}

// ---------------- embedding ----------------
__global__ void embed_kernel(const float* __restrict__ past_x,
                             const float* __restrict__ past_y,
                             const float* __restrict__ future_x,
                             const float* __restrict__ W_emb,
                             const float* __restrict__ b_emb,
                             float* __restrict__ h) {
    int idx = blockIdx.x * blockDim.x + threadIdx.x;
    if (idx >= kB * kS * kD) return;
    int d = idx % kD;
    int s = (idx / kD) % kS;
    int b = idx / (kD * kS);
    float feat[kXD + 1];
    if (s < kSP) {
#pragma unroll
        for (int j = 0; j < kXD; j++) feat[j] = past_x[((size_t)b * kSP + s) * kXD + j];
        feat[kXD] = past_y[(size_t)b * kSP + s];
    } else {
        int sf = s - kSP;
#pragma unroll
        for (int j = 0; j < kXD; j++) feat[j] = future_x[((size_t)b * kSF + sf) * kXD + j];
        feat[kXD] = past_y[(size_t)b * kSP + (kSP - 1)];
    }
    float acc = b_emb[d];
#pragma unroll
    for (int j = 0; j < kXD + 1; j++) acc += feat[j] * W_emb[(size_t)j * kD + d];
    h[idx] = acc;
}

// ---------------- layernorm (block per row, 128 threads) ----------------
__global__ void ln_kernel(const float* __restrict__ x, float* __restrict__ y,
                          const float* __restrict__ g, const float* __restrict__ bb) {
    __shared__ float red[8];
    int row = blockIdx.x;
    int t = threadIdx.x;
    const float4 xv = ((const float4*)(x + (size_t)row * kD))[t];
    float s = xv.x + xv.y + xv.z + xv.w;
#pragma unroll
    for (int o = 16; o; o >>= 1) s += __shfl_xor_sync(0xffffffffu, s, o);
    if ((t & 31) == 0) red[t >> 5] = s;
    __syncthreads();
    float mean = (red[0] + red[1] + red[2] + red[3]) * (1.0f / kD);
    float dx = xv.x - mean, dy = xv.y - mean, dz = xv.z - mean, dw = xv.w - mean;
    float s2 = dx * dx + dy * dy + dz * dz + dw * dw;
#pragma unroll
    for (int o = 16; o; o >>= 1) s2 += __shfl_xor_sync(0xffffffffu, s2, o);
    if ((t & 31) == 0) red[4 + (t >> 5)] = s2;
    __syncthreads();
    float var = (red[4] + red[5] + red[6] + red[7]) * (1.0f / kD);
    float rstd = rsqrtf(var + 1e-5f);
    const float4 gg = ((const float4*)g)[t];
    const float4 bv = ((const float4*)bb)[t];
    float4 o4;
    o4.x = dx * rstd * gg.x + bv.x;
    o4.y = dy * rstd * gg.y + bv.y;
    o4.z = dz * rstd * gg.z + bv.z;
    o4.w = dw * rstd * gg.w + bv.w;
    ((float4*)(y + (size_t)row * kD))[t] = o4;
}

// ---------------- routing scores: shuffle-free, bit-identical reduction tree ----------------
__global__ __launch_bounds__(128) void score2_kernel(
    const float* __restrict__ q, const float* __restrict__ k,
    const float* __restrict__ means, float* __restrict__ scores) {
    int blk = blockIdx.x;
    int inst = blk >> 10;
    int rem = blk & 1023;
    int b = rem >> 7;
    int h = (rem >> 4) & 7;
    int st = rem & 15;
    const float* src = inst ? k : q;
    float* dst = scores + (size_t)inst * kNBHC * kS;
    int t = threadIdx.x;
    int s = st * 128 + t;

    __shared__ float ms[kC * kDH];
    for (int i = t; i < kC * kDH; i += 128)
        ms[i] = means[(size_t)h * kC * kDH + i];
    __syncthreads();

    float qv[kDH];
    const float4* qrow = (const float4*)(src + ((size_t)b * kS + s) * kD + h * kDH);
#pragma unroll
    for (int i = 0; i < kDH / 4; i++) ((float4*)qv)[i] = qrow[i];

    float p[32];
#pragma unroll
    for (int l = 0; l < 32; l++) p[l] = qv[l] * qv[l] + qv[l + 32] * qv[l + 32];
#pragma unroll
    for (int o = 16; o; o >>= 1)
#pragma unroll
        for (int l = 0; l < o; l++) p[l] += p[l + o];
    float rn = rsqrtf(p[0] + 1e-8f);

    float* out = dst + (((size_t)b * kH + h) * kC) * kS + s;
#pragma unroll
    for (int c = 0; c < kC; c++) {
        const float* mrow = ms + c * kDH;
        float pp[32];
#pragma unroll
        for (int l = 0; l < 32; l++) pp[l] = qv[l] * mrow[l] + qv[l + 32] * mrow[l + 32];
#pragma unroll
        for (int o = 16; o; o >>= 1)
#pragma unroll
            for (int l = 0; l < o; l++) pp[l] += pp[l + o];
        out[(size_t)c * kS] = pp[0] * rn;
    }
}

// ---------------- top-W: bitonic network, warp-local inner substages ----------------
// Substage j: writer of element i may be thread (i^j)&511 -> cross-warp iff j>=32.
// Within a stage, once j<=16 all traffic is warp-local -> __syncwarp suffices.
// EVERY stage ends with __syncthreads (next stage starts cross-warp).
__global__ __launch_bounds__(512) void topk_kernel(const float* __restrict__ scores,
                                                   int* __restrict__ idxout) {
    __shared__ unsigned long long keys[kS];
    int blk = blockIdx.x;
    const float* sp = scores + (size_t)blk * kS;
    for (int i = threadIdx.x; i < kS; i += 512) {
        unsigned u = __float_as_uint(sp[i]);
        u = (u & 0x80000000u) ? ~u : (u | 0x80000000u);
        keys[i] = ((unsigned long long)u << 32) | (unsigned)i;
    }
    __syncthreads();
    for (int k = 2; k <= 1024; k <<= 1) {
        for (int j = k >> 1; j > 0; j >>= 1) {
            for (int i = threadIdx.x; i < kS; i += 512) {
                int ixj = i ^ j;
                if (ixj > i) {
                    unsigned long long a = keys[i], b = keys[ixj];
                    bool up = ((i & k) == 0);
                    bool sw = up ? (a < b) : (a > b);
                    if (sw) { keys[i] = b; keys[ixj] = a; }
                }
            }
            if (j > 16 || j == 1) __syncthreads();   // j==1: stage end, next stage is cross-warp
            else __syncwarp();
        }
    }
    // final merge: prefix bitonic splits keep the top-half multiset each step
#pragma unroll
    for (int half = 1024; half >= 128; half >>= 1) {
        for (int i = threadIdx.x; i < half; i += 512) {
            unsigned long long a = keys[i], b = keys[i + half];
            if (a < b) { keys[i] = b; keys[i + half] = a; }
        }
        __syncthreads();
    }
    if (threadIdx.x < kW)
        idxout[(size_t)blk * kW + threadIdx.x] = (int)(keys[threadIdx.x] & 0xffffffffu);
}

// ---------------- within-cluster attention + scatter-add ----------------
__global__ __launch_bounds__(128) void attn_kernel(
    const float* __restrict__ q, const float* __restrict__ k, const float* __restrict__ v,
    const int* __restrict__ iq, const int* __restrict__ ik,
    float* __restrict__ attnout, float* __restrict__ cnt) {
    int blk = blockIdx.x;
    int h = (blk / kC) % kH;
    int b = blk / (kC * kH);
    extern __shared__ float smem[];
    float* ks = smem;
    float* vs = smem + kW * kDH;
    int t = threadIdx.x;
    const int* ikp = ik + (size_t)blk * kW;
    const int* iqp = iq + (size_t)blk * kW;
    {
        int sk = ikp[t];
        const float4* krow = (const float4*)(k + ((size_t)b * kS + sk) * kD + h * kDH);
        const float4* vrow = (const float4*)(v + ((size_t)b * kS + sk) * kD + h * kDH);
        float4* ksr = (float4*)(ks + (size_t)t * kDH);
        float4* vsr = (float4*)(vs + (size_t)t * kDH);
#pragma unroll
        for (int i = 0; i < kDH / 4; i++) { ksr[i] = krow[i]; vsr[i] = vrow[i]; }
    }
    __syncthreads();
    int sq = iqp[t];
    float qreg[kDH];
    {
        const float4* qrow = (const float4*)(q + ((size_t)b * kS + sq) * kD + h * kDH);
#pragma unroll
        for (int i = 0; i < kDH / 4; i++) ((float4*)qreg)[i] = qrow[i];
    }
    float m = -1e30f, l = 0.f;
    float accv[kDH];
#pragma unroll
    for (int d = 0; d < kDH; d++) accv[d] = 0.f;
    const float scale = 0.125f;

    for (int j = 0; j < kW; j++) {
        const float* kj = ks + (size_t)j * kDH;
        float s0 = 0, s1 = 0, s2 = 0, s3 = 0;
#pragma unroll
        for (int d = 0; d < kDH; d += 4) {
            s0 += qreg[d + 0] * kj[d + 0];
            s1 += qreg[d + 1] * kj[d + 1];
            s2 += qreg[d + 2] * kj[d + 2];
            s3 += qreg[d + 3] * kj[d + 3];
        }
        float s = (s0 + s1 + s2 + s3) * scale;
        const float* vj = vs + (size_t)j * kDH;
        if (s > m) {
            float corr = __expf(m - s);
            l = fmaf(l, corr, 1.0f);
#pragma unroll
            for (int d = 0; d < kDH; d++) accv[d] = fmaf(accv[d], corr, vj[d]);
            m = s;
        } else {
            float p = __expf(s - m);
            l += p;
#pragma unroll
            for (int d = 0; d < kDH; d++) accv[d] = fmaf(p, vj[d], accv[d]);
        }
    }
    float inv = 1.0f / l;
    float* orow = attnout + ((size_t)b * kS + sq) * kD + h * kDH;
#pragma unroll
    for (int d = 0; d < kDH; d++) atomicAdd(orow + d, accv[d] * inv);
    atomicAdd(cnt + ((size_t)b * kH + h) * kS + sq, 1.0f);
}

// ---------------- fused final LN + heads (block per future row) ----------------
__global__ __launch_bounds__(128) void lnhead_kernel(
    const float* __restrict__ x, const float* __restrict__ g, const float* __restrict__ bb,
    const float* __restrict__ Wm, const float* __restrict__ bm,
    const float* __restrict__ Ws, const float* __restrict__ bsd,
    float* __restrict__ out) {
    __shared__ float red[8];
    __shared__ float rowv[kD];
    int blk = blockIdx.x;                                 // 0..kB*kSF-1
    int row = (blk / kSF) * kS + kSP + (blk % kSF);
    int t = threadIdx.x;
    const float4 xv = ((const float4*)(x + (size_t)row * kD))[t];
    float s = xv.x + xv.y + xv.z + xv.w;
#pragma unroll
    for (int o = 16; o; o >>= 1) s += __shfl_xor_sync(0xffffffffu, s, o);
    if ((t & 31) == 0) red[t >> 5] = s;
    __syncthreads();
    float mean = (red[0] + red[1] + red[2] + red[3]) * (1.0f / kD);
    float dx = xv.x - mean, dy = xv.y - mean, dz = xv.z - mean, dw = xv.w - mean;
    float s2 = dx * dx + dy * dy + dz * dz + dw * dw;
#pragma unroll
    for (int o = 16; o; o >>= 1) s2 += __shfl_xor_sync(0xffffffffu, s2, o);
    if ((t & 31) == 0) red[4 + (t >> 5)] = s2;
    __syncthreads();
    float var = (red[4] + red[5] + red[6] + red[7]) * (1.0f / kD);
    float rstd = rsqrtf(var + 1e-5f);
    const float4 gg = ((const float4*)g)[t];
    const float4 bv = ((const float4*)bb)[t];
    float4 o4;
    o4.x = dx * rstd * gg.x + bv.x;
    o4.y = dy * rstd * gg.y + bv.y;
    o4.z = dz * rstd * gg.z + bv.z;
    o4.w = dw * rstd * gg.w + bv.w;
    ((float4*)rowv)[t] = o4;
    __syncthreads();
    if (t < 32) {
        float mdot = 0.f, sdot = 0.f;
        for (int d = t; d < kD; d += 32) {
            float v = rowv[d];
            mdot += v * Wm[d];
            sdot += v * Ws[d];
        }
#pragma unroll
        for (int o = 16; o; o >>= 1) {
            mdot += __shfl_xor_sync(0xffffffffu, mdot, o);
            sdot += __shfl_xor_sync(0xffffffffu, sdot, o);
        }
        if (t == 0) {
            out[blk] = mdot + bm[0];
            float ls = sdot + bsd[0];
            float sp = fmaxf(ls, 0.f) + log1pf(__expf(-fabsf(ls)));
            out[(size_t)kB * kSF + blk] = 0.01f + 0.99f * sp;
        }
    }
}

// ---------------- host orchestration ----------------
static void launch_gemm(const float* A, const float* Bm, const float* bias,
                        const float* res, const float* acnt, float* C,
                        int M, int N, int K, int act) {
    dim3 grid(N / TBN, M / TBM);
    sgemm_kernel<<<grid, 256>>>(A, Bm, bias, res, acnt, C, M, N, K, act);
}

extern "C" void kernel_launch(void* const* d_in, const int* in_sizes, int n_in,
                              void* d_out, int out_size) {
    const float* past_x   = (const float*)d_in[0];
    const float* past_y   = (const float*)d_in[1];
    const float* future_x = (const float*)d_in[2];
    const float* W_emb    = (const float*)d_in[3];
    const float* b_emb    = (const float*)d_in[4];
    const float* ln1_g    = (const float*)d_in[5];
    const float* ln1_b    = (const float*)d_in[6];
    const float* Wq       = (const float*)d_in[7];
    const float* Wk       = (const float*)d_in[8];
    const float* Wv       = (const float*)d_in[9];
    const float* Wo       = (const float*)d_in[10];
    const float* means    = (const float*)d_in[11];
    const float* ln2_g    = (const float*)d_in[12];
    const float* ln2_b    = (const float*)d_in[13];
    const float* W1       = (const float*)d_in[14];
    const float* b1       = (const float*)d_in[15];
    const float* W2       = (const float*)d_in[16];
    const float* b2       = (const float*)d_in[17];
    const float* lnf_g    = (const float*)d_in[18];
    const float* lnf_b    = (const float*)d_in[19];
    const float* W_mean   = (const float*)d_in[20];
    const float* b_mean   = (const float*)d_in[21];
    const float* W_std    = (const float*)d_in[22];
    const float* b_std    = (const float*)d_in[23];

    void *ph, *pln, *pq, *pk, *pv, *pac, *pffn, *pscores, *pidx;
    cudaGetSymbolAddress(&ph, g_h);
    cudaGetSymbolAddress(&pln, g_ln);
    cudaGetSymbolAddress(&pq, g_q);
    cudaGetSymbolAddress(&pk, g_k);
    cudaGetSymbolAddress(&pv, g_v);
    cudaGetSymbolAddress(&pac, g_attncnt);
    cudaGetSymbolAddress(&pffn, g_ffn);
    cudaGetSymbolAddress(&pscores, g_scores);
    cudaGetSymbolAddress(&pidx, g_idx);
    float* h    = (float*)ph;
    float* ln   = (float*)pln;
    float* q    = (float*)pq;
    float* k    = (float*)pk;
    float* v    = (float*)pv;
    float* attn = (float*)pac;
    float* cnt  = (float*)pac + (size_t)kB * kS * kD;
    float* ffn  = (float*)pffn;
    float* scr  = (float*)pscores;
    int*   iq   = (int*)pidx;
    int*   ik   = (int*)pidx + (size_t)kNBHC * kW;

    const int attn_smem = 2 * kW * kDH * (int)sizeof(float);  // 64 KB
    cudaFuncSetAttribute(attn_kernel, cudaFuncAttributeMaxDynamicSharedMemorySize, attn_smem);

    {
        int total = kB * kS * kD;
        embed_kernel<<<(total + 255) / 256, 256>>>(past_x, past_y, future_x, W_emb, b_emb, h);
    }

    const size_t attncnt_bytes = ((size_t)kB * kS * kD + (size_t)kB * kH * kS) * sizeof(float);

    for (int l = 0; l < kL; l++) {
        const float* mns = means + (size_t)l * kH * kC * kDH;
        // --- attention block ---
        ln_kernel<<<kM, 128>>>(h, ln, ln1_g + (size_t)l * kD, ln1_b + (size_t)l * kD);
        {
            dim3 grid(kD / TBN, kM / TBM, 3);
            qkv_gemm_kernel<<<grid, 256>>>(
                ln, Wq + (size_t)l * kD * kD, Wk + (size_t)l * kD * kD, Wv + (size_t)l * kD * kD,
                q, k, v, kM, kD, kD);
        }

        score2_kernel<<<2 * kB * kH * (kS / 128), 128>>>(q, k, mns, scr);
        topk_kernel<<<2 * kNBHC, 512>>>(scr, (int*)pidx);

        cudaMemsetAsync(attn, 0, attncnt_bytes, 0);
        attn_kernel<<<kNBHC, 128, attn_smem>>>(q, k, v, iq, ik, attn, cnt);

        // h = h + (attn/cnt) @ Wo
        launch_gemm(attn, Wo + (size_t)l * kD * kD, nullptr, h, cnt, h, kM, kD, kD, 0);

        // --- FFN block ---
        ln_kernel<<<kM, 128>>>(h, ln, ln2_g + (size_t)l * kD, ln2_b + (size_t)l * kD);
        launch_gemm(ln, W1 + (size_t)l * kD * kFF, b1 + (size_t)l * kFF, nullptr, nullptr, ffn, kM, kFF, kD, 1);
        launch_gemm(ffn, W2 + (size_t)l * kFF * kD, b2 + (size_t)l * kD, h, nullptr, h, kM, kD, kFF, 0);
    }

    // fused final LN + heads over the future half only
    lnhead_kernel<<<kB * kSF, 128>>>(h, lnf_g, lnf_b, W_mean, b_mean, W_std, b_std,
                                     (float*)d_out);
}